// round 3
// baseline (speedup 1.0000x reference)
#include <cuda_runtime.h>

// Top 3 rows of the 4x4 SE3 matrix, row-major 3x4. Row 3 is implicitly [0,0,0,1].
__device__ float g_M[12];

// One-thread kernel: build the SE3 exp matrix exactly as the fp32 reference does.
__global__ void se3_build_matrix(const float* __restrict__ w,
                                 const float* __restrict__ v,
                                 const float* __restrict__ theta_p) {
    if (threadIdx.x != 0 || blockIdx.x != 0) return;

    const float wx = w[0], wy = w[1], wz = w[2];
    const float theta = theta_p[0];
    const float s = sinf(theta);
    const float c = cosf(theta);
    const float omc = 1.0f - c;       // 1 - cos(theta)
    const float tms = theta - s;      // theta - sin(theta)

    // K = skew(w)
    float K[9] = { 0.0f, -wz,   wy,
                   wz,    0.0f, -wx,
                  -wy,    wx,   0.0f };
    // KK = K @ K
    float KK[9];
    #pragma unroll
    for (int r = 0; r < 3; r++) {
        #pragma unroll
        for (int col = 0; col < 3; col++) {
            float acc = 0.0f;
            #pragma unroll
            for (int k = 0; k < 3; k++) acc += K[r * 3 + k] * K[k * 3 + col];
            KK[r * 3 + col] = acc;
        }
    }

    float R[9], V[9];
    #pragma unroll
    for (int r = 0; r < 3; r++) {
        #pragma unroll
        for (int col = 0; col < 3; col++) {
            const float I = (r == col) ? 1.0f : 0.0f;
            R[r * 3 + col] = I + s * K[r * 3 + col] + omc * KK[r * 3 + col];
            V[r * 3 + col] = I * theta + omc * K[r * 3 + col] + tms * KK[r * 3 + col];
        }
    }

    const float vx = v[0], vy = v[1], vz = v[2];
    #pragma unroll
    for (int r = 0; r < 3; r++) {
        g_M[r * 4 + 0] = R[r * 3 + 0];
        g_M[r * 4 + 1] = R[r * 3 + 1];
        g_M[r * 4 + 2] = R[r * 3 + 2];
        g_M[r * 4 + 3] = V[r * 3 + 0] * vx + V[r * 3 + 1] * vy + V[r * 3 + 2] * vz;
    }
}

// Streaming transform: y[r][i] = sum_c M[r][c] * x[c][i]; y[3][i] = x[3][i].
// x, y laid out [4, N] row-major; processed as float4 columns (n4 = N/4).
__global__ __launch_bounds__(256)
void se3_apply_vec4(const float4* __restrict__ x, float4* __restrict__ y, int n4) {
    const int i = blockIdx.x * blockDim.x + threadIdx.x;
    if (i >= n4) return;

    // Broadcast matrix (L2 hits; 12 uniform loads)
    const float m00 = g_M[0],  m01 = g_M[1],  m02 = g_M[2],  m03 = g_M[3];
    const float m10 = g_M[4],  m11 = g_M[5],  m12 = g_M[6],  m13 = g_M[7];
    const float m20 = g_M[8],  m21 = g_M[9],  m22 = g_M[10], m23 = g_M[11];

    const float4 x0 = __ldcs(x + 0 * (size_t)n4 + i);
    const float4 x1 = __ldcs(x + 1 * (size_t)n4 + i);
    const float4 x2 = __ldcs(x + 2 * (size_t)n4 + i);
    const float4 x3 = __ldcs(x + 3 * (size_t)n4 + i);

    float4 y0, y1, y2;
    y0.x = m00 * x0.x + m01 * x1.x + m02 * x2.x + m03 * x3.x;
    y0.y = m00 * x0.y + m01 * x1.y + m02 * x2.y + m03 * x3.y;
    y0.z = m00 * x0.z + m01 * x1.z + m02 * x2.z + m03 * x3.z;
    y0.w = m00 * x0.w + m01 * x1.w + m02 * x2.w + m03 * x3.w;

    y1.x = m10 * x0.x + m11 * x1.x + m12 * x2.x + m13 * x3.x;
    y1.y = m10 * x0.y + m11 * x1.y + m12 * x2.y + m13 * x3.y;
    y1.z = m10 * x0.z + m11 * x1.z + m12 * x2.z + m13 * x3.z;
    y1.w = m10 * x0.w + m11 * x1.w + m12 * x2.w + m13 * x3.w;

    y2.x = m20 * x0.x + m21 * x1.x + m22 * x2.x + m23 * x3.x;
    y2.y = m20 * x0.y + m21 * x1.y + m22 * x2.y + m23 * x3.y;
    y2.z = m20 * x0.z + m21 * x1.z + m22 * x2.z + m23 * x3.z;
    y2.w = m20 * x0.w + m21 * x1.w + m22 * x2.w + m23 * x3.w;

    __stcs(y + 0 * (size_t)n4 + i, y0);
    __stcs(y + 1 * (size_t)n4 + i, y1);
    __stcs(y + 2 * (size_t)n4 + i, y2);
    __stcs(y + 3 * (size_t)n4 + i, x3);   // bottom row [0,0,0,1]
}

// Scalar tail (N not divisible by 4) — defensive; N=16M is divisible.
__global__ void se3_apply_tail(const float* __restrict__ x, float* __restrict__ y,
                               int N, int start) {
    const int i = start + blockIdx.x * blockDim.x + threadIdx.x;
    if (i >= N) return;
    const float a = x[0 * (size_t)N + i];
    const float b = x[1 * (size_t)N + i];
    const float cc = x[2 * (size_t)N + i];
    const float d = x[3 * (size_t)N + i];
    y[0 * (size_t)N + i] = g_M[0] * a + g_M[1] * b + g_M[2]  * cc + g_M[3]  * d;
    y[1 * (size_t)N + i] = g_M[4] * a + g_M[5] * b + g_M[6]  * cc + g_M[7]  * d;
    y[2 * (size_t)N + i] = g_M[8] * a + g_M[9] * b + g_M[10] * cc + g_M[11] * d;
    y[3 * (size_t)N + i] = d;
}

extern "C" void kernel_launch(void* const* d_in, const int* in_sizes, int n_in,
                              void* d_out, int out_size) {
    const float* x     = (const float*)d_in[0];   // [4, N]
    const float* w     = (const float*)d_in[1];   // [3]
    const float* v     = (const float*)d_in[2];   // [3]
    const float* theta = (const float*)d_in[3];   // scalar

    const int N  = in_sizes[0] / 4;
    const int n4 = N / 4;
    const int rem = N - n4 * 4;

    se3_build_matrix<<<1, 32>>>(w, v, theta);

    if (n4 > 0) {
        const int threads = 256;
        const int blocks = (n4 + threads - 1) / threads;
        se3_apply_vec4<<<blocks, threads>>>((const float4*)x, (float4*)d_out, n4);
    }
    if (rem > 0) {
        se3_apply_tail<<<1, 128>>>(x, (float*)d_out, N, n4 * 4);
    }
}